// round 1
// baseline (speedup 1.0000x reference)
#include <cuda_runtime.h>
#include <math.h>

// ---------------- problem constants ----------------
#define BATCH   16
#define SLEN    512
#define DIM     512
#define VOCAB   32000
#define KBEAM   4
#define TMAX    64
#define SOS_TOK 1
#define EOS_TOK 2
#define PAD_TOK 0
#define NEGV    (-1e9f)
#define ATT_SCALE 0.044194173824159216f   // 1/sqrt(512)

// ---------------- persistent scratch (no allocs allowed) ----------------
__device__ float g_encK[(size_t)BATCH * SLEN * DIM];      // 16 MB
__device__ float g_h[64 * DIM];                            // decoder states (B*K rows)
__device__ float g_logits[(size_t)64 * VOCAB];             // 8.2 MB
__device__ float g_cand_lp[64 * 4];
__device__ int   g_cand_v[64 * 4];
__device__ float g_scores[BATCH * KBEAM];
__device__ int   g_fin[BATCH * KBEAM];
__device__ int   g_cur[BATCH * KBEAM];
__device__ int   g_seqs[BATCH * KBEAM * TMAX];

// ---------------- generic fp32 GEMM: C[M,N] = A[M,K] @ B[K,N] (+bias) ----------------
// BM=64, BN=128, BK=32, 256 threads, each thread 8 rows x 4 cols.
// Requires M%64==0, N%128==0, K%32==0 (true for all uses here).
#define GBM 64
#define GBN 128
#define GBK 32

__global__ __launch_bounds__(256) void sgemm_kernel(
    const float* __restrict__ A, const float* __restrict__ B,
    const float* __restrict__ bias, float* __restrict__ C,
    int M, int N, int K)
{
    __shared__ float As[GBK][GBM];
    __shared__ float Bs[GBK][GBN];

    const int tid = threadIdx.x;
    const int tx  = tid & 31;        // col group: cols tx*4 .. tx*4+3
    const int ty  = tid >> 5;        // row group: rows ty*8 .. ty*8+7
    const int m0  = blockIdx.y * GBM;
    const int n0  = blockIdx.x * GBN;

    float acc[8][4];
#pragma unroll
    for (int i = 0; i < 8; i++)
#pragma unroll
        for (int j = 0; j < 4; j++) acc[i][j] = 0.f;

    for (int k0 = 0; k0 < K; k0 += GBK) {
        // load A tile (64x32), coalesced on k
#pragma unroll
        for (int i = 0; i < 8; i++) {
            int l = tid + i * 256;
            int m = l >> 5, k = l & 31;
            As[k][m] = A[(size_t)(m0 + m) * K + (k0 + k)];
        }
        // load B tile (32x128), coalesced on n
#pragma unroll
        for (int i = 0; i < 16; i++) {
            int l = tid + i * 256;
            int k = l >> 7, n = l & 127;
            Bs[k][n] = B[(size_t)(k0 + k) * N + (n0 + n)];
        }
        __syncthreads();
#pragma unroll
        for (int k = 0; k < GBK; k++) {
            float4 bv = *(const float4*)&Bs[k][tx * 4];
#pragma unroll
            for (int i = 0; i < 8; i++) {
                float av = As[k][ty * 8 + i];
                acc[i][0] += av * bv.x;
                acc[i][1] += av * bv.y;
                acc[i][2] += av * bv.z;
                acc[i][3] += av * bv.w;
            }
        }
        __syncthreads();
    }

    const int n = n0 + tx * 4;
    float4 bb = make_float4(0.f, 0.f, 0.f, 0.f);
    if (bias) {
        bb.x = bias[n + 0]; bb.y = bias[n + 1]; bb.z = bias[n + 2]; bb.w = bias[n + 3];
    }
#pragma unroll
    for (int i = 0; i < 8; i++) {
        int m = m0 + ty * 8 + i;
        float4 r;
        r.x = acc[i][0] + bb.x;
        r.y = acc[i][1] + bb.y;
        r.z = acc[i][2] + bb.z;
        r.w = acc[i][3] + bb.w;
        *(float4*)&C[(size_t)m * N + n] = r;
    }
}

// ---------------- attention + h = e + ctx ----------------
// One block per batch element b; handles all nbeam beams so encK/enc are read once.
// 512 threads.
__global__ __launch_bounds__(512) void attn_kernel(
    const float* __restrict__ enc, const int* __restrict__ lens,
    const float* __restrict__ emb, const float* __restrict__ Wq,
    int nbeam, int force_tok)
{
    __shared__ float e4[4][DIM];
    __shared__ float q4[4][DIM];
    __shared__ float att[4][SLEN];
    __shared__ float red[512];

    const int b   = blockIdx.x;
    const int tid = threadIdx.x;
    const int len = lens[b];

    // load embeddings of current tokens (zero-fill unused beam rows)
    for (int kk = 0; kk < 4; kk++) {
        if (kk < nbeam) {
            int tok = (force_tok >= 0) ? force_tok : g_cur[b * nbeam + kk];
            e4[kk][tid] = emb[(size_t)tok * DIM + tid];
        } else {
            e4[kk][tid] = 0.f;
        }
    }
    __syncthreads();

    // q = e @ Wq   (thread j computes q[*][j])
    {
        float acc0 = 0.f, acc1 = 0.f, acc2 = 0.f, acc3 = 0.f;
        const int j = tid;
        for (int d = 0; d < DIM; d++) {
            float w = Wq[d * DIM + j];
            acc0 += e4[0][d] * w;
            acc1 += e4[1][d] * w;
            acc2 += e4[2][d] * w;
            acc3 += e4[3][d] * w;
        }
        q4[0][j] = acc0; q4[1][j] = acc1; q4[2][j] = acc2; q4[3][j] = acc3;
    }
    __syncthreads();

    // att[kk][s] = scale * q[kk] . encK[b,s,:]  (thread s)
    {
        const int s = tid;
        const float4* ek = (const float4*)(g_encK + ((size_t)b * SLEN + s) * DIM);
        float acc[4] = {0.f, 0.f, 0.f, 0.f};
        for (int d4 = 0; d4 < DIM / 4; d4++) {
            float4 kv = ek[d4];
#pragma unroll
            for (int kk = 0; kk < 4; kk++) {
                float4 qv = *(const float4*)&q4[kk][d4 * 4];
                acc[kk] += qv.x * kv.x + qv.y * kv.y + qv.z * kv.z + qv.w * kv.w;
            }
        }
        bool valid = s < len;
#pragma unroll
        for (int kk = 0; kk < 4; kk++)
            att[kk][s] = valid ? acc[kk] * ATT_SCALE : NEGV;
    }
    __syncthreads();

    // softmax over s for each beam row
    for (int kk = 0; kk < 4; kk++) {
        red[tid] = att[kk][tid];
        __syncthreads();
        for (int off = 256; off > 0; off >>= 1) {
            if (tid < off) red[tid] = fmaxf(red[tid], red[tid + off]);
            __syncthreads();
        }
        float m = red[0];
        __syncthreads();
        float p = expf(att[kk][tid] - m);
        red[tid] = p;
        __syncthreads();
        for (int off = 256; off > 0; off >>= 1) {
            if (tid < off) red[tid] += red[tid + off];
            __syncthreads();
        }
        float ssum = red[0];
        __syncthreads();
        att[kk][tid] = p / ssum;
        __syncthreads();
    }

    // ctx[kk][d] = sum_s p[kk][s] * enc[b,s,d];  h = e + ctx   (thread d)
    {
        const int d = tid;
        const float* eb = enc + (size_t)b * SLEN * DIM;
        float acc[4] = {0.f, 0.f, 0.f, 0.f};
        for (int s4 = 0; s4 < SLEN / 4; s4++) {
            float ev0 = eb[(size_t)(s4 * 4 + 0) * DIM + d];
            float ev1 = eb[(size_t)(s4 * 4 + 1) * DIM + d];
            float ev2 = eb[(size_t)(s4 * 4 + 2) * DIM + d];
            float ev3 = eb[(size_t)(s4 * 4 + 3) * DIM + d];
#pragma unroll
            for (int kk = 0; kk < 4; kk++) {
                float4 pv = *(const float4*)&att[kk][s4 * 4];
                acc[kk] += pv.x * ev0 + pv.y * ev1 + pv.z * ev2 + pv.w * ev3;
            }
        }
        for (int kk = 0; kk < nbeam; kk++)
            g_h[(size_t)(b * nbeam + kk) * DIM + d] = e4[kk][d] + acc[kk];
    }
}

// ---------------- per-row top-4 + logsumexp over vocab ----------------
__device__ __forceinline__ bool pref(float v1, int i1, float v2, int i2) {
    return v1 > v2 || (v1 == v2 && i1 < i2);
}

__global__ __launch_bounds__(256) void topk_lse_kernel()
{
    const int row = blockIdx.x;
    const int tid = threadIdx.x;
    const float* base = g_logits + (size_t)row * VOCAB;

    float m = -INFINITY, s = 0.f;
    float tv[4] = {-INFINITY, -INFINITY, -INFINITY, -INFINITY};
    int   ti[4] = {0x7fffffff, 0x7fffffff, 0x7fffffff, 0x7fffffff};

    for (int v = tid; v < VOCAB; v += 256) {
        float x = base[v];
        // online logsumexp
        if (x > m) { s = s * __expf(m - x) + 1.f; m = x; }
        else       { s += __expf(x - m); }
        // top-4 insert (strict > keeps earliest index on ties)
        if (x > tv[3]) {
            int p;
            if (x > tv[0]) p = 0;
            else if (x > tv[1]) p = 1;
            else if (x > tv[2]) p = 2;
            else p = 3;
            for (int q = 3; q > p; q--) { tv[q] = tv[q - 1]; ti[q] = ti[q - 1]; }
            tv[p] = x; ti[p] = v;
        }
    }

    __shared__ float sm[256], ss[256];
    __shared__ float stv[256][4];
    __shared__ int   sti[256][4];
    sm[tid] = m; ss[tid] = s;
#pragma unroll
    for (int j = 0; j < 4; j++) { stv[tid][j] = tv[j]; sti[tid][j] = ti[j]; }
    __syncthreads();

    for (int off = 128; off > 0; off >>= 1) {
        if (tid < off) {
            // lse merge
            float m1 = sm[tid], s1 = ss[tid];
            float m2 = sm[tid + off], s2 = ss[tid + off];
            float M = fmaxf(m1, m2);
            ss[tid] = s1 * __expf(m1 - M) + s2 * __expf(m2 - M);
            sm[tid] = M;
            // top-4 merge of two sorted lists
            float av[4], bvv[4], ov[4];
            int   ai[4], bi[4], oi[4];
#pragma unroll
            for (int j = 0; j < 4; j++) {
                av[j] = stv[tid][j];        ai[j] = sti[tid][j];
                bvv[j] = stv[tid + off][j]; bi[j] = sti[tid + off][j];
            }
            int ia = 0, ib = 0;
#pragma unroll
            for (int p = 0; p < 4; p++) {
                if (pref(av[ia], ai[ia], bvv[ib], bi[ib])) { ov[p] = av[ia]; oi[p] = ai[ia]; ia++; }
                else                                       { ov[p] = bvv[ib]; oi[p] = bi[ib]; ib++; }
            }
#pragma unroll
            for (int j = 0; j < 4; j++) { stv[tid][j] = ov[j]; sti[tid][j] = oi[j]; }
        }
        __syncthreads();
    }

    if (tid == 0) {
        float lse = sm[0] + logf(ss[0]);
#pragma unroll
        for (int j = 0; j < 4; j++) {
            g_cand_lp[row * 4 + j] = stv[0][j] - lse;
            g_cand_v[row * 4 + j]  = sti[0][j];
        }
    }
}

// ---------------- step-1 init: expand SOS into K beams ----------------
__global__ void init_kernel()
{
    int b = threadIdx.x;
    if (b >= BATCH) return;
    for (int k = 0; k < KBEAM; k++) {
        float lp = g_cand_lp[b * 4 + k];
        int   tk = g_cand_v[b * 4 + k];
        g_scores[b * KBEAM + k] = lp;
        g_fin[b * KBEAM + k]    = (tk == EOS_TOK) ? 1 : 0;
        g_cur[b * KBEAM + k]    = tk;
        for (int pos = 0; pos < TMAX; pos++) {
            int v = PAD_TOK;
            if (pos == 0) v = SOS_TOK;
            else if (pos == 1) v = tk;
            g_seqs[(b * KBEAM + k) * TMAX + pos] = v;
        }
    }
}

// ---------------- per-step beam combine (top-4 over K*K) ----------------
__global__ void combine_kernel(int t)
{
    int b = threadIdx.x;
    if (b >= BATCH) return;

    float sc[4]; int fin[4];
    for (int k = 0; k < 4; k++) {
        sc[k]  = g_scores[b * 4 + k];
        fin[k] = g_fin[b * 4 + k];
    }

    float tot[16]; int tokc[16];
    for (int k = 0; k < 4; k++) {
        for (int j = 0; j < 4; j++) {
            float lp; int tk;
            if (fin[k]) { lp = (j == 0) ? 0.f : NEGV; tk = PAD_TOK; }
            else {
                lp = g_cand_lp[(b * 4 + k) * 4 + j];
                tk = g_cand_v[(b * 4 + k) * 4 + j];
            }
            tot[k * 4 + j]  = sc[k] + lp;
            tokc[k * 4 + j] = tk;
        }
    }

    int used[16];
    for (int i = 0; i < 16; i++) used[i] = 0;
    int selb[4], selt[4]; float selsc[4];
    for (int p = 0; p < 4; p++) {
        int best = -1; float bv = -INFINITY;
        for (int i = 0; i < 16; i++) {
            if (!used[i] && tot[i] > bv) { bv = tot[i]; best = i; }   // strict > => lowest index on tie
        }
        used[best] = 1;
        selsc[p] = bv;
        selb[p]  = best >> 2;
        selt[p]  = tokc[best];
    }

    int oldseq[4][TMAX];
    for (int k = 0; k < 4; k++)
        for (int pos = 0; pos < TMAX; pos++)
            oldseq[k][pos] = g_seqs[(b * 4 + k) * TMAX + pos];

    for (int p = 0; p < 4; p++) {
        int bi = selb[p], tk = selt[p];
        for (int pos = 0; pos < TMAX; pos++)
            g_seqs[(b * 4 + p) * TMAX + pos] = (pos == t) ? tk : oldseq[bi][pos];
        g_fin[b * 4 + p]    = fin[bi] | (tk == EOS_TOK);
        g_cur[b * 4 + p]    = tk;
        g_scores[b * 4 + p] = selsc[p];
    }
}

// ---------------- final: pick best beam, write output ----------------
__global__ void final_kernel(float* __restrict__ out)
{
    int b = threadIdx.x;
    if (b >= BATCH) return;
    float bv = -INFINITY; int bi = 0;
    for (int k = 0; k < KBEAM; k++) {
        float v = g_scores[b * 4 + k];
        if (v > bv) { bv = v; bi = k; }    // first max == jnp.argmax
    }
    for (int pos = 0; pos < TMAX; pos++)
        out[b * TMAX + pos] = (float)g_seqs[(b * 4 + bi) * TMAX + pos];
    out[BATCH * TMAX + b] = bv;
}

// ---------------- launch ----------------
extern "C" void kernel_launch(void* const* d_in, const int* in_sizes, int n_in,
                              void* d_out, int out_size)
{
    const float* enc  = (const float*)d_in[0];   // [16,512,512]
    const int*   lens = (const int*)  d_in[1];   // [16]
    const float* emb  = (const float*)d_in[2];   // [32000,512]
    const float* Wq   = (const float*)d_in[3];   // [512,512]
    const float* Wk   = (const float*)d_in[4];   // [512,512]
    const float* Wfc  = (const float*)d_in[5];   // [512,32000]
    const float* bfc  = (const float*)d_in[6];   // [32000]
    float* out = (float*)d_out;

    float *p_encK, *p_h, *p_logits;
    cudaGetSymbolAddress((void**)&p_encK,   g_encK);
    cudaGetSymbolAddress((void**)&p_h,      g_h);
    cudaGetSymbolAddress((void**)&p_logits, g_logits);

    // encK = enc @ Wk : M=8192, N=512, K=512
    sgemm_kernel<<<dim3(DIM / GBN, (BATCH * SLEN) / GBM), 256>>>(
        enc, Wk, nullptr, p_encK, BATCH * SLEN, DIM, DIM);

    // step 1: SOS -> top-K over vocab
    attn_kernel<<<BATCH, 512>>>(enc, lens, emb, Wq, 1, SOS_TOK);
    sgemm_kernel<<<dim3(VOCAB / GBN, 1), 256>>>(p_h, Wfc, bfc, p_logits, 64, VOCAB, DIM);
    topk_lse_kernel<<<BATCH, 256>>>();
    init_kernel<<<1, 32>>>();

    // steps 2..63
    for (int t = 2; t < TMAX; t++) {
        attn_kernel<<<BATCH, 512>>>(enc, lens, emb, Wq, KBEAM, -1);
        sgemm_kernel<<<dim3(VOCAB / GBN, 1), 256>>>(p_h, Wfc, bfc, p_logits, 64, VOCAB, DIM);
        topk_lse_kernel<<<BATCH * KBEAM, 256>>>();
        combine_kernel<<<1, 32>>>(t);
    }

    final_kernel<<<1, 32>>>(out);
}